// round 1
// baseline (speedup 1.0000x reference)
#include <cuda_runtime.h>
#include <math_constants.h>

// Problem constants
#define B_   8
#define H_   56
#define W_   56
#define C_   256
#define CI_  128
#define N_   3136           // H*W
#define M_   1568           // N/2 after maxpool
#define ROWS_ (B_*N_)       // 25088

// ---------------- scratch (device globals; no allocations allowed) --------
__device__ float d_theta[B_*N_*CI_];     // [row][128]
__device__ float d_tmp  [B_*N_*2*CI_];   // [row][0:128)=phi proj, [128:256)=g proj
__device__ float d_phi  [B_*M_*CI_];
__device__ float d_g    [B_*M_*CI_];
__device__ float d_y    [B_*N_*CI_];

// ===========================================================================
// K1: projections.  C[25088,384] = X[25088,256] @ [w_theta | w_phi | w_g]
// 128x128 tile per block, BK=8, 256 threads, 8x8 micro-tile (strided mapping)
// ===========================================================================
__global__ __launch_bounds__(256)
void k_proj(const float* __restrict__ X,
            const float* __restrict__ Wt,
            const float* __restrict__ Wp,
            const float* __restrict__ Wg)
{
    __shared__ float As[8][128];
    __shared__ float Bs[8][128];

    const int bx = blockIdx.x;           // 0,1,2 -> theta,phi,g
    const int by = blockIdx.y;           // row tile
    const int t  = threadIdx.x;
    const float* Wsel = (bx == 0) ? Wt : ((bx == 1) ? Wp : Wg);
    const int row0 = by * 128;

    const int ar  = t >> 1;              // 0..127
    const int ac4 = (t & 1) * 4;         // 0 or 4
    const int bkr = t >> 5;              // 0..7
    const int bj4 = (t & 31) * 4;        // 0..124
    const int tr  = t >> 4;              // 0..15
    const int tc  = t & 15;              // 0..15

    float acc[8][8];
#pragma unroll
    for (int i = 0; i < 8; i++)
#pragma unroll
        for (int j = 0; j < 8; j++) acc[i][j] = 0.f;

    for (int k0 = 0; k0 < 256; k0 += 8) {
        float4 av = *(const float4*)&X[(size_t)(row0 + ar) * 256 + k0 + ac4];
        As[ac4 + 0][ar] = av.x; As[ac4 + 1][ar] = av.y;
        As[ac4 + 2][ar] = av.z; As[ac4 + 3][ar] = av.w;
        float4 bv = *(const float4*)&Wsel[(size_t)(k0 + bkr) * 128 + bj4];
        *(float4*)&Bs[bkr][bj4] = bv;
        __syncthreads();
#pragma unroll
        for (int k = 0; k < 8; k++) {
            float a[8], b[8];
#pragma unroll
            for (int i = 0; i < 8; i++) a[i] = As[k][tr + 16 * i];
#pragma unroll
            for (int j = 0; j < 8; j++) b[j] = Bs[k][tc + 16 * j];
#pragma unroll
            for (int i = 0; i < 8; i++)
#pragma unroll
                for (int j = 0; j < 8; j++) acc[i][j] = fmaf(a[i], b[j], acc[i][j]);
        }
        __syncthreads();
    }

#pragma unroll
    for (int i = 0; i < 8; i++) {
        int r = row0 + tr + 16 * i;
#pragma unroll
        for (int j = 0; j < 8; j++) {
            int c = tc + 16 * j;
            if (bx == 0) d_theta[(size_t)r * 128 + c] = acc[i][j];
            else         d_tmp[(size_t)r * 256 + (bx - 1) * 128 + c] = acc[i][j];
        }
    }
}

// ===========================================================================
// K2: non-overlapping maxpool (stride 2) along N for phi and g projections
// ===========================================================================
__global__ __launch_bounds__(256)
void k_pool()
{
    int idx = blockIdx.x * 256 + threadIdx.x;
    const int total = B_ * M_ * CI_;
    if (idx >= total) return;
    int ci = idx & (CI_ - 1);
    int t2 = idx >> 7;                 // b*M + m
    int m  = t2 % M_;
    int b  = t2 / M_;
    size_t row0 = ((size_t)b * N_ + 2 * m) * 256;
    float p0 = d_tmp[row0 + ci];
    float p1 = d_tmp[row0 + 256 + ci];
    float g0 = d_tmp[row0 + 128 + ci];
    float g1 = d_tmp[row0 + 384 + ci];
    d_phi[idx] = fmaxf(p0, p1);
    d_g[idx]   = fmaxf(g0, g1);
}

// ===========================================================================
// K3: fused attention (flash style).  Per block: 64 query rows of one batch.
//   stream M in tiles of 32: S = Th @ PhT, online softmax, Y += P @ G
//   Y kept in registers (4 rows x 8 cols per thread), written to d_y.
// smem layout (dynamic): th[64][129], ph[32][129], gs[32][129], ps[64][33],
//                        ms[64], ls[64], as_[64]
// ===========================================================================
#define K3_SMEM_FLOATS (64*129 + 32*129 + 32*129 + 64*33 + 3*64)
#define K3_SMEM_BYTES  (K3_SMEM_FLOATS * 4)

__global__ __launch_bounds__(256)
void k_attn()
{
    extern __shared__ float smem[];
    float* th  = smem;                 // 64*129
    float* ph  = th + 64 * 129;        // 32*129
    float* gs  = ph + 32 * 129;        // 32*129
    float* ps  = gs + 32 * 129;        // 64*33
    float* ms  = ps + 64 * 33;         // 64
    float* ls  = ms + 64;              // 64
    float* as_ = ls + 64;              // 64

    const int b  = blockIdx.y;
    const int n0 = blockIdx.x * 64;
    const int t  = threadIdx.x;
    const int ty = t >> 4;             // 0..15  -> rows ty*4 .. ty*4+3
    const int tx = t & 15;             // 0..15  -> cols tx + 16*j

    // ---- load theta tile [64][128] ----
    {
        int r  = t >> 2;               // 0..63
        int kq = (t & 3) * 32;
        const float* src = &d_theta[((size_t)b * N_ + n0 + r) * 128 + kq];
#pragma unroll
        for (int q = 0; q < 8; q++) {
            float4 v = *(const float4*)&src[q * 4];
            float* dst = &th[r * 129 + kq + q * 4];
            dst[0] = v.x; dst[1] = v.y; dst[2] = v.z; dst[3] = v.w;
        }
    }
    if (t < 64) { ms[t] = -1e30f; ls[t] = 0.f; }

    float y[4][8];
#pragma unroll
    for (int i = 0; i < 4; i++)
#pragma unroll
        for (int j = 0; j < 8; j++) y[i][j] = 0.f;

    for (int mt = 0; mt < M_ / 32; mt++) {
        const int m0 = mt * 32;
        __syncthreads();   // previous iteration finished with ph/gs

        // ---- load phi,g tiles [32][128] ----
        {
            int lm = t >> 3;           // 0..31
            int kq = (t & 7) * 16;
            const float* sp = &d_phi[((size_t)b * M_ + m0 + lm) * 128 + kq];
            const float* sg = &d_g  [((size_t)b * M_ + m0 + lm) * 128 + kq];
#pragma unroll
            for (int q = 0; q < 4; q++) {
                float4 v = *(const float4*)&sp[q * 4];
                float* d = &ph[lm * 129 + kq + q * 4];
                d[0] = v.x; d[1] = v.y; d[2] = v.z; d[3] = v.w;
                float4 w = *(const float4*)&sg[q * 4];
                float* e = &gs[lm * 129 + kq + q * 4];
                e[0] = w.x; e[1] = w.y; e[2] = w.z; e[3] = w.w;
            }
        }
        __syncthreads();

        // ---- S[64][32] = Th @ PhT ; thread: rows ty*4+i, cols j*16+tx ----
        float s_acc[4][2];
#pragma unroll
        for (int i = 0; i < 4; i++) { s_acc[i][0] = 0.f; s_acc[i][1] = 0.f; }
#pragma unroll 4
        for (int k = 0; k < 128; k++) {
            float a[4], bb[2];
#pragma unroll
            for (int i = 0; i < 4; i++) a[i] = th[(ty * 4 + i) * 129 + k];
#pragma unroll
            for (int j = 0; j < 2; j++) bb[j] = ph[(j * 16 + tx) * 129 + k];
#pragma unroll
            for (int i = 0; i < 4; i++) {
                s_acc[i][0] = fmaf(a[i], bb[0], s_acc[i][0]);
                s_acc[i][1] = fmaf(a[i], bb[1], s_acc[i][1]);
            }
        }
#pragma unroll
        for (int i = 0; i < 4; i++) {
            ps[(ty * 4 + i) * 33 + tx]      = s_acc[i][0];
            ps[(ty * 4 + i) * 33 + 16 + tx] = s_acc[i][1];
        }
        __syncthreads();

        // ---- online softmax: one thread per row (t < 64) ----
        if (t < 64) {
            float mx = -1e30f;
#pragma unroll
            for (int kk = 0; kk < 32; kk++) mx = fmaxf(mx, ps[t * 33 + kk]);
            float mold = ms[t];
            float mnew = fmaxf(mold, mx);
            float alpha = __expf(mold - mnew);
            float lsum = 0.f;
#pragma unroll
            for (int kk = 0; kk < 32; kk++) {
                float p = __expf(ps[t * 33 + kk] - mnew);
                ps[t * 33 + kk] = p;
                lsum += p;
            }
            ls[t] = ls[t] * alpha + lsum;
            ms[t] = mnew;
            as_[t] = alpha;
        }
        __syncthreads();

        // ---- Y = Y*alpha + P @ G ----
        float al[4];
#pragma unroll
        for (int i = 0; i < 4; i++) al[i] = as_[ty * 4 + i];
#pragma unroll
        for (int i = 0; i < 4; i++)
#pragma unroll
            for (int j = 0; j < 8; j++) y[i][j] *= al[i];

#pragma unroll 4
        for (int kk = 0; kk < 32; kk++) {
            float p[4], g[8];
#pragma unroll
            for (int i = 0; i < 4; i++) p[i] = ps[(ty * 4 + i) * 33 + kk];
#pragma unroll
            for (int j = 0; j < 8; j++) g[j] = gs[kk * 129 + j * 16 + tx];
#pragma unroll
            for (int i = 0; i < 4; i++)
#pragma unroll
                for (int j = 0; j < 8; j++) y[i][j] = fmaf(p[i], g[j], y[i][j]);
        }
    }
    __syncthreads();

    // ---- normalize + store ----
    float inv[4];
#pragma unroll
    for (int i = 0; i < 4; i++) inv[i] = 1.f / ls[ty * 4 + i];
#pragma unroll
    for (int i = 0; i < 4; i++) {
        size_t rowg = (size_t)b * N_ + n0 + ty * 4 + i;
#pragma unroll
        for (int j = 0; j < 8; j++)
            d_y[rowg * 128 + j * 16 + tx] = y[i][j] * inv[i];
    }
}

// ===========================================================================
// K4: out = x + Y @ w_final.   Y[25088,128] @ Wf[128,256]
// ===========================================================================
__global__ __launch_bounds__(256)
void k_final(const float* __restrict__ X,
             const float* __restrict__ Wf,
             float* __restrict__ out)
{
    __shared__ float As[8][128];
    __shared__ float Bs[8][128];

    const int bx = blockIdx.x;           // 0,1 -> col halves of 256
    const int by = blockIdx.y;
    const int t  = threadIdx.x;
    const int row0 = by * 128;

    const int ar  = t >> 1;
    const int ac4 = (t & 1) * 4;
    const int bkr = t >> 5;
    const int bj4 = (t & 31) * 4;
    const int tr  = t >> 4;
    const int tc  = t & 15;

    float acc[8][8];
#pragma unroll
    for (int i = 0; i < 8; i++)
#pragma unroll
        for (int j = 0; j < 8; j++) acc[i][j] = 0.f;

    for (int k0 = 0; k0 < 128; k0 += 8) {
        float4 av = *(const float4*)&d_y[(size_t)(row0 + ar) * 128 + k0 + ac4];
        As[ac4 + 0][ar] = av.x; As[ac4 + 1][ar] = av.y;
        As[ac4 + 2][ar] = av.z; As[ac4 + 3][ar] = av.w;
        float4 bv = *(const float4*)&Wf[(size_t)(k0 + bkr) * 256 + bx * 128 + bj4];
        *(float4*)&Bs[bkr][bj4] = bv;
        __syncthreads();
#pragma unroll
        for (int k = 0; k < 8; k++) {
            float a[8], b[8];
#pragma unroll
            for (int i = 0; i < 8; i++) a[i] = As[k][tr + 16 * i];
#pragma unroll
            for (int j = 0; j < 8; j++) b[j] = Bs[k][tc + 16 * j];
#pragma unroll
            for (int i = 0; i < 8; i++)
#pragma unroll
                for (int j = 0; j < 8; j++) acc[i][j] = fmaf(a[i], b[j], acc[i][j]);
        }
        __syncthreads();
    }

#pragma unroll
    for (int i = 0; i < 8; i++) {
        size_t r = row0 + tr + 16 * i;
#pragma unroll
        for (int j = 0; j < 8; j++) {
            int c = bx * 128 + tc + 16 * j;
            out[r * 256 + c] = X[r * 256 + c] + acc[i][j];
        }
    }
}

// ===========================================================================
extern "C" void kernel_launch(void* const* d_in, const int* in_sizes, int n_in,
                              void* d_out, int out_size)
{
    const float* x  = (const float*)d_in[0];
    const float* wt = (const float*)d_in[1];
    const float* wp = (const float*)d_in[2];
    const float* wg = (const float*)d_in[3];
    const float* wf = (const float*)d_in[4];
    float* out = (float*)d_out;

    // K1: projections
    {
        dim3 grid(3, ROWS_ / 128);
        k_proj<<<grid, 256>>>(x, wt, wp, wg);
    }
    // K2: maxpool
    {
        int total = B_ * M_ * CI_;
        k_pool<<<(total + 255) / 256, 256>>>();
    }
    // K3: fused attention
    {
        cudaFuncSetAttribute(k_attn, cudaFuncAttributeMaxDynamicSharedMemorySize,
                             K3_SMEM_BYTES);
        dim3 grid(N_ / 64, B_);
        k_attn<<<grid, 256, K3_SMEM_BYTES>>>();
    }
    // K4: final projection + residual
    {
        dim3 grid(2, ROWS_ / 128);
        k_final<<<grid, 256>>>(x, wf, out);
    }
}

// round 3
// speedup vs baseline: 2.3354x; 2.3354x over previous
#include <cuda_runtime.h>
#include <cuda_bf16.h>
#include <cstdint>

// Problem constants
#define B_    8
#define C_    256
#define CI_   128
#define N_    3136
#define M_    1568
#define MPAD_ 1600            // 25*64
#define ROWS_ (B_*N_)         // 25088
#define ITERS 25
#define KV    64

// ---------------- scratch (device globals) --------------------------------
__device__ float         d_tmp [ROWS_*2*CI_];       // phi/g projections fp32
__device__ __nv_bfloat16 d_th_hi[ROWS_*CI_];
__device__ __nv_bfloat16 d_th_lo[ROWS_*CI_];
__device__ __nv_bfloat16 d_ph_hi[B_*MPAD_*CI_];     // [b][m][ci]
__device__ __nv_bfloat16 d_ph_lo[B_*MPAD_*CI_];
__device__ __nv_bfloat16 d_g_hi [B_*MPAD_*CI_];     // [b][m][ci]
__device__ __nv_bfloat16 d_g_lo [B_*MPAD_*CI_];
__device__ float         d_y   [ROWS_*CI_];

// ======================= helpers ==========================================
__device__ __forceinline__ uint32_t smem_u32(const void* p) {
    uint32_t a;
    asm("{ .reg .u64 t; cvta.to.shared.u64 t, %1; cvt.u32.u64 %0, t; }"
        : "=r"(a) : "l"(p));
    return a;
}

__device__ __forceinline__ void ldsm4(uint32_t r[4], uint32_t addr) {
    asm volatile("ldmatrix.sync.aligned.m8n8.x4.shared.b16 {%0,%1,%2,%3}, [%4];"
                 : "=r"(r[0]), "=r"(r[1]), "=r"(r[2]), "=r"(r[3]) : "r"(addr));
}
__device__ __forceinline__ void ldsm4t(uint32_t r[4], uint32_t addr) {
    asm volatile("ldmatrix.sync.aligned.m8n8.x4.trans.shared.b16 {%0,%1,%2,%3}, [%4];"
                 : "=r"(r[0]), "=r"(r[1]), "=r"(r[2]), "=r"(r[3]) : "r"(addr));
}
__device__ __forceinline__ void mma16816(float c[4],
                                         uint32_t a0, uint32_t a1, uint32_t a2, uint32_t a3,
                                         uint32_t b0, uint32_t b1) {
    asm volatile(
        "mma.sync.aligned.m16n8k16.row.col.f32.bf16.bf16.f32 "
        "{%0,%1,%2,%3}, {%4,%5,%6,%7}, {%8,%9}, {%0,%1,%2,%3};"
        : "+f"(c[0]), "+f"(c[1]), "+f"(c[2]), "+f"(c[3])
        : "r"(a0), "r"(a1), "r"(a2), "r"(a3), "r"(b0), "r"(b1));
}

__device__ __forceinline__ uint32_t pack_bf16_hi(float x, float y) {
    __nv_bfloat16 hx = __float2bfloat16(x), hy = __float2bfloat16(y);
    return (uint32_t)__bfloat16_as_ushort(hx) |
           ((uint32_t)__bfloat16_as_ushort(hy) << 16);
}
__device__ __forceinline__ uint32_t pack_bf16_lo(float x, float y) {
    __nv_bfloat16 hx = __float2bfloat16(x), hy = __float2bfloat16(y);
    __nv_bfloat16 lx = __float2bfloat16(x - __bfloat162float(hx));
    __nv_bfloat16 ly = __float2bfloat16(y - __bfloat162float(hy));
    return (uint32_t)__bfloat16_as_ushort(lx) |
           ((uint32_t)__bfloat16_as_ushort(ly) << 16);
}

// SMEM layout (byte offsets): row stride 272B (128 bf16 + 16B pad)
#define SB_      272
#define OFF_THH  0
#define OFF_THL  34816
#define OFF_PHH  69632
#define OFF_PHL  87040
#define OFF_GH   104448
#define OFF_GL   121856
#define SM_TOTAL 139264

// ===========================================================================
// K1: projections (fp32 FFMA).  theta -> split bf16; phi/g proj -> fp32 tmp.
// ===========================================================================
__global__ __launch_bounds__(256)
void k_proj(const float* __restrict__ X,
            const float* __restrict__ Wt,
            const float* __restrict__ Wp,
            const float* __restrict__ Wg)
{
    __shared__ float As[8][128];
    __shared__ float Bs[8][128];

    const int bx = blockIdx.x;
    const int by = blockIdx.y;
    const int t  = threadIdx.x;
    const float* Wsel = (bx == 0) ? Wt : ((bx == 1) ? Wp : Wg);
    const int row0 = by * 128;

    const int ar  = t >> 1;
    const int ac4 = (t & 1) * 4;
    const int bkr = t >> 5;
    const int bj4 = (t & 31) * 4;
    const int tr  = t >> 4;
    const int tc  = t & 15;

    float acc[8][8];
#pragma unroll
    for (int i = 0; i < 8; i++)
#pragma unroll
        for (int j = 0; j < 8; j++) acc[i][j] = 0.f;

    for (int k0 = 0; k0 < 256; k0 += 8) {
        float4 av = *(const float4*)&X[(size_t)(row0 + ar) * 256 + k0 + ac4];
        As[ac4 + 0][ar] = av.x; As[ac4 + 1][ar] = av.y;
        As[ac4 + 2][ar] = av.z; As[ac4 + 3][ar] = av.w;
        float4 bv = *(const float4*)&Wsel[(size_t)(k0 + bkr) * 128 + bj4];
        *(float4*)&Bs[bkr][bj4] = bv;
        __syncthreads();
#pragma unroll
        for (int k = 0; k < 8; k++) {
            float a[8], b[8];
#pragma unroll
            for (int i = 0; i < 8; i++) a[i] = As[k][tr + 16 * i];
#pragma unroll
            for (int j = 0; j < 8; j++) b[j] = Bs[k][tc + 16 * j];
#pragma unroll
            for (int i = 0; i < 8; i++)
#pragma unroll
                for (int j = 0; j < 8; j++) acc[i][j] = fmaf(a[i], b[j], acc[i][j]);
        }
        __syncthreads();
    }

#pragma unroll
    for (int i = 0; i < 8; i++) {
        int r = row0 + tr + 16 * i;
#pragma unroll
        for (int j = 0; j < 8; j++) {
            int c = tc + 16 * j;
            float v = acc[i][j];
            if (bx == 0) {
                __nv_bfloat16 h = __float2bfloat16(v);
                d_th_hi[(size_t)r * 128 + c] = h;
                d_th_lo[(size_t)r * 128 + c] = __float2bfloat16(v - __bfloat162float(h));
            } else {
                d_tmp[(size_t)r * 256 + (bx - 1) * 128 + c] = v;
            }
        }
    }
}

// ===========================================================================
// K2: maxpool + bf16 split; phi and g both stored [b][m][ci], zero padded
// ===========================================================================
__global__ __launch_bounds__(256)
void k_pool()
{
    int idx = blockIdx.x * 256 + threadIdx.x;
    const int total = B_ * MPAD_ * CI_;
    if (idx >= total) return;
    int ci = idx & (CI_ - 1);
    int t2 = idx >> 7;
    int m  = t2 % MPAD_;
    int b  = t2 / MPAD_;
    float pv = 0.f, gv = 0.f;
    if (m < M_) {
        size_t row0 = ((size_t)b * N_ + 2 * m) * 256;
        pv = fmaxf(d_tmp[row0 + ci],       d_tmp[row0 + 256 + ci]);
        gv = fmaxf(d_tmp[row0 + 128 + ci], d_tmp[row0 + 384 + ci]);
    }
    __nv_bfloat16 ph = __float2bfloat16(pv);
    __nv_bfloat16 gh = __float2bfloat16(gv);
    size_t pidx = ((size_t)b * MPAD_ + m) * CI_ + ci;
    d_ph_hi[pidx] = ph;
    d_ph_lo[pidx] = __float2bfloat16(pv - __bfloat162float(ph));
    d_g_hi[pidx]  = gh;
    d_g_lo[pidx]  = __float2bfloat16(gv - __bfloat162float(gh));
}

// ===========================================================================
// K3: mma.sync flash attention, split-bf16 3-chain, online softmax,
//     Y accumulators in registers.  CTA = 128 q-rows, 8 warps x 16 rows.
// ===========================================================================
__global__ __launch_bounds__(256, 1)
void k_attn3()
{
    extern __shared__ char smem[];
    const uint32_t sb = smem_u32(smem);
    const int b  = blockIdx.y;
    const int n0 = blockIdx.x * 128;
    const int t  = threadIdx.x;
    const int w  = t >> 5;
    const int lane = t & 31;
    const int tg  = lane >> 3;        // ldmatrix address group
    const int tr8 = lane & 7;

    // ldmatrix per-thread address components
    const int aA_row  = ((tg & 1) << 3) + tr8;   // A / G(trans) pattern
    const int aA_colb = (tg & 2) * 8;            // 0 or 16 bytes
    const int bp_row  = ((tg & 2) << 2) + tr8;   // phi B pattern
    const int bp_colb = (tg & 1) * 16;

    const uint32_t thA = sb + OFF_THH + (uint32_t)(16 * w + aA_row) * SB_ + aA_colb;
    const uint32_t tlA = sb + OFF_THL + (uint32_t)(16 * w + aA_row) * SB_ + aA_colb;
    const uint32_t phB = sb + OFF_PHH + (uint32_t)bp_row * SB_ + bp_colb;
    const uint32_t plB = sb + OFF_PHL + (uint32_t)bp_row * SB_ + bp_colb;
    const uint32_t ghB = sb + OFF_GH  + (uint32_t)aA_row * SB_ + aA_colb;
    const uint32_t glB = sb + OFF_GL  + (uint32_t)aA_row * SB_ + aA_colb;

    // ---- load theta tile [128][128] hi+lo ----
#pragma unroll
    for (int q = 0; q < 8; q++) {
        int i = t + 256 * q;
        int r = i >> 4, c8 = (i & 15) * 8;
        int n = n0 + r; if (n > N_ - 1) n = N_ - 1;
        size_t gidx = ((size_t)b * N_ + n) * 128 + c8;
        *(uint4*)(smem + OFF_THH + r * SB_ + c8 * 2) = *(const uint4*)(d_th_hi + gidx);
        *(uint4*)(smem + OFF_THL + r * SB_ + c8 * 2) = *(const uint4*)(d_th_lo + gidx);
    }

    float yv[16][4];
#pragma unroll
    for (int f = 0; f < 16; f++)
#pragma unroll
        for (int j = 0; j < 4; j++) yv[f][j] = 0.f;
    float mA = -1e30f, mB = -1e30f, lA = 0.f, lB = 0.f;

    for (int mt = 0; mt < ITERS; mt++) {
        const int m0 = mt * KV;
        __syncthreads();
        // ---- load phi/g tiles [64][128] hi+lo ----
#pragma unroll
        for (int q = 0; q < 4; q++) {
            int i = t + 256 * q;
            int r = i >> 4, c8 = (i & 15) * 8;
            size_t gidx = ((size_t)b * MPAD_ + m0 + r) * 128 + c8;
            int so = r * SB_ + c8 * 2;
            *(uint4*)(smem + OFF_PHH + so) = *(const uint4*)(d_ph_hi + gidx);
            *(uint4*)(smem + OFF_PHL + so) = *(const uint4*)(d_ph_lo + gidx);
            *(uint4*)(smem + OFF_GH  + so) = *(const uint4*)(d_g_hi  + gidx);
            *(uint4*)(smem + OFF_GL  + so) = *(const uint4*)(d_g_lo  + gidx);
        }
        __syncthreads();

        // ---- S[16][64] per warp: 3 chains ----
        float sf[8][4];
#pragma unroll
        for (int f = 0; f < 8; f++)
#pragma unroll
            for (int j = 0; j < 4; j++) sf[f][j] = 0.f;

#pragma unroll
        for (int k = 0; k < 8; k++) {
            uint32_t ah[4], al[4];
            ldsm4(ah, thA + k * 32);
            ldsm4(al, tlA + k * 32);
#pragma unroll
            for (int nb = 0; nb < 4; nb++) {
                uint32_t bh[4];
                ldsm4(bh, phB + (uint32_t)(nb * 16) * SB_ + k * 32);
                mma16816(sf[2 * nb],     ah[0], ah[1], ah[2], ah[3], bh[0], bh[1]);
                mma16816(sf[2 * nb + 1], ah[0], ah[1], ah[2], ah[3], bh[2], bh[3]);
                mma16816(sf[2 * nb],     al[0], al[1], al[2], al[3], bh[0], bh[1]);
                mma16816(sf[2 * nb + 1], al[0], al[1], al[2], al[3], bh[2], bh[3]);
            }
#pragma unroll
            for (int nb = 0; nb < 4; nb++) {
                uint32_t bl[4];
                ldsm4(bl, plB + (uint32_t)(nb * 16) * SB_ + k * 32);
                mma16816(sf[2 * nb],     ah[0], ah[1], ah[2], ah[3], bl[0], bl[1]);
                mma16816(sf[2 * nb + 1], ah[0], ah[1], ah[2], ah[3], bl[2], bl[3]);
            }
        }

        // ---- online softmax (rows t/4 and t/4+8 of warp strip) ----
        float mxA = -1e30f, mxB = -1e30f;
#pragma unroll
        for (int f = 0; f < 8; f++) {
            mxA = fmaxf(mxA, fmaxf(sf[f][0], sf[f][1]));
            mxB = fmaxf(mxB, fmaxf(sf[f][2], sf[f][3]));
        }
        mxA = fmaxf(mxA, __shfl_xor_sync(0xffffffffu, mxA, 1));
        mxA = fmaxf(mxA, __shfl_xor_sync(0xffffffffu, mxA, 2));
        mxB = fmaxf(mxB, __shfl_xor_sync(0xffffffffu, mxB, 1));
        mxB = fmaxf(mxB, __shfl_xor_sync(0xffffffffu, mxB, 2));
        float mnA = fmaxf(mA, mxA), mnB = fmaxf(mB, mxB);
        float aAc = __expf(mA - mnA), aBc = __expf(mB - mnB);
        mA = mnA; mB = mnB;
        lA *= aAc; lB *= aBc;
#pragma unroll
        for (int f = 0; f < 16; f++) {
            yv[f][0] *= aAc; yv[f][1] *= aAc;
            yv[f][2] *= aBc; yv[f][3] *= aBc;
        }

        uint32_t pah[4][4], pal[4][4];
#pragma unroll
        for (int ks = 0; ks < 4; ks++) {
#pragma unroll
            for (int h = 0; h < 2; h++) {
                int f = 2 * ks + h;
                float p0 = __expf(sf[f][0] - mA);
                float p1 = __expf(sf[f][1] - mA);
                float p2 = __expf(sf[f][2] - mB);
                float p3 = __expf(sf[f][3] - mB);
                lA += p0 + p1; lB += p2 + p3;
                pah[ks][0 + 2 * h] = pack_bf16_hi(p0, p1);
                pah[ks][1 + 2 * h] = pack_bf16_hi(p2, p3);
                pal[ks][0 + 2 * h] = pack_bf16_lo(p0, p1);
                pal[ks][1 + 2 * h] = pack_bf16_lo(p2, p3);
            }
        }

        // ---- Y += P @ G : 3 chains ----
#pragma unroll
        for (int ks = 0; ks < 4; ks++) {
            const uint32_t gb = (uint32_t)(ks * 16) * SB_;
#pragma unroll
            for (int ng = 0; ng < 8; ng++) {
                uint32_t bh[4];
                ldsm4t(bh, ghB + gb + ng * 32);
                mma16816(yv[2 * ng],     pah[ks][0], pah[ks][1], pah[ks][2], pah[ks][3], bh[0], bh[1]);
                mma16816(yv[2 * ng + 1], pah[ks][0], pah[ks][1], pah[ks][2], pah[ks][3], bh[2], bh[3]);
                mma16816(yv[2 * ng],     pal[ks][0], pal[ks][1], pal[ks][2], pal[ks][3], bh[0], bh[1]);
                mma16816(yv[2 * ng + 1], pal[ks][0], pal[ks][1], pal[ks][2], pal[ks][3], bh[2], bh[3]);
            }
#pragma unroll
            for (int ng = 0; ng < 8; ng++) {
                uint32_t bl[4];
                ldsm4t(bl, glB + gb + ng * 32);
                mma16816(yv[2 * ng],     pah[ks][0], pah[ks][1], pah[ks][2], pah[ks][3], bl[0], bl[1]);
                mma16816(yv[2 * ng + 1], pah[ks][0], pah[ks][1], pah[ks][2], pah[ks][3], bl[2], bl[3]);
            }
        }
    }

    // ---- final l reduce + normalize + store ----
    lA += __shfl_xor_sync(0xffffffffu, lA, 1);
    lA += __shfl_xor_sync(0xffffffffu, lA, 2);
    lB += __shfl_xor_sync(0xffffffffu, lB, 1);
    lB += __shfl_xor_sync(0xffffffffu, lB, 2);
    const float liA = 1.f / lA, liB = 1.f / lB;

    const int nA = n0 + 16 * w + (lane >> 2);
    const int nB = nA + 8;
    const int cb = 2 * (lane & 3);
    if (nA < N_) {
        float* dst = &d_y[((size_t)b * N_ + nA) * 128];
#pragma unroll
        for (int nf = 0; nf < 16; nf++) {
            float2 v = { yv[nf][0] * liA, yv[nf][1] * liA };
            *(float2*)&dst[nf * 8 + cb] = v;
        }
    }
    if (nB < N_) {
        float* dst = &d_y[((size_t)b * N_ + nB) * 128];
#pragma unroll
        for (int nf = 0; nf < 16; nf++) {
            float2 v = { yv[nf][2] * liB, yv[nf][3] * liB };
            *(float2*)&dst[nf * 8 + cb] = v;
        }
    }
}

// ===========================================================================
// K4: out = x + Y @ w_final  (fp32)
// ===========================================================================
__global__ __launch_bounds__(256)
void k_final(const float* __restrict__ X,
             const float* __restrict__ Wf,
             float* __restrict__ out)
{
    __shared__ float As[8][128];
    __shared__ float Bs[8][128];

    const int bx = blockIdx.x;
    const int by = blockIdx.y;
    const int t  = threadIdx.x;
    const int row0 = by * 128;

    const int ar  = t >> 1;
    const int ac4 = (t & 1) * 4;
    const int bkr = t >> 5;
    const int bj4 = (t & 31) * 4;
    const int tr  = t >> 4;
    const int tc  = t & 15;

    float acc[8][8];
#pragma unroll
    for (int i = 0; i < 8; i++)
#pragma unroll
        for (int j = 0; j < 8; j++) acc[i][j] = 0.f;

    for (int k0 = 0; k0 < 128; k0 += 8) {
        float4 av = *(const float4*)&d_y[(size_t)(row0 + ar) * 128 + k0 + ac4];
        As[ac4 + 0][ar] = av.x; As[ac4 + 1][ar] = av.y;
        As[ac4 + 2][ar] = av.z; As[ac4 + 3][ar] = av.w;
        float4 bv = *(const float4*)&Wf[(size_t)(k0 + bkr) * 256 + bx * 128 + bj4];
        *(float4*)&Bs[bkr][bj4] = bv;
        __syncthreads();
#pragma unroll
        for (int k = 0; k < 8; k++) {
            float a[8], b[8];
#pragma unroll
            for (int i = 0; i < 8; i++) a[i] = As[k][tr + 16 * i];
#pragma unroll
            for (int j = 0; j < 8; j++) b[j] = Bs[k][tc + 16 * j];
#pragma unroll
            for (int i = 0; i < 8; i++)
#pragma unroll
                for (int j = 0; j < 8; j++) acc[i][j] = fmaf(a[i], b[j], acc[i][j]);
        }
        __syncthreads();
    }

#pragma unroll
    for (int i = 0; i < 8; i++) {
        size_t r = row0 + tr + 16 * i;
#pragma unroll
        for (int j = 0; j < 8; j++) {
            int c = bx * 128 + tc + 16 * j;
            out[r * 256 + c] = X[r * 256 + c] + acc[i][j];
        }
    }
}

// ===========================================================================
extern "C" void kernel_launch(void* const* d_in, const int* in_sizes, int n_in,
                              void* d_out, int out_size)
{
    const float* x  = (const float*)d_in[0];
    const float* wt = (const float*)d_in[1];
    const float* wp = (const float*)d_in[2];
    const float* wg = (const float*)d_in[3];
    const float* wf = (const float*)d_in[4];
    float* out = (float*)d_out;

    {
        dim3 grid(3, ROWS_ / 128);
        k_proj<<<grid, 256>>>(x, wt, wp, wg);
    }
    {
        int total = B_ * MPAD_ * CI_;
        k_pool<<<(total + 255) / 256, 256>>>();
    }
    {
        cudaFuncSetAttribute(k_attn3, cudaFuncAttributeMaxDynamicSharedMemorySize,
                             SM_TOTAL);
        dim3 grid(25, B_);
        k_attn3<<<grid, 256, SM_TOTAL>>>();
    }
    {
        dim3 grid(2, ROWS_ / 128);
        k_final<<<grid, 256>>>(x, wf, out);
    }
}

// round 4
// speedup vs baseline: 3.0118x; 1.2896x over previous
#include <cuda_runtime.h>
#include <cuda_bf16.h>
#include <cstdint>

// Problem constants
#define B_    8
#define C_    256
#define CI_   128
#define N_    3136
#define M_    1568
#define MPAD_ 1600            // 25*64
#define ROWS_ (B_*N_)         // 25088
#define PROWS_ (B_*M_)        // 12544 pooled rows (flattened)
#define ITERS 25
#define KV    64

// ---------------- scratch (device globals; zero-initialized) --------------
__device__ __nv_bfloat16 d_th_hi[ROWS_*CI_];
__device__ __nv_bfloat16 d_th_lo[ROWS_*CI_];
__device__ __nv_bfloat16 d_ph_hi[B_*MPAD_*CI_];     // [b][m][ci], pad rows stay 0
__device__ __nv_bfloat16 d_ph_lo[B_*MPAD_*CI_];
__device__ __nv_bfloat16 d_g_hi [B_*MPAD_*CI_];
__device__ __nv_bfloat16 d_g_lo [B_*MPAD_*CI_];
__device__ __nv_bfloat16 d_y_hi [ROWS_*CI_];
__device__ __nv_bfloat16 d_y_lo [ROWS_*CI_];

// ======================= helpers ==========================================
__device__ __forceinline__ uint32_t smem_u32(const void* p) {
    uint32_t a;
    asm("{ .reg .u64 t; cvta.to.shared.u64 t, %1; cvt.u32.u64 %0, t; }"
        : "=r"(a) : "l"(p));
    return a;
}
__device__ __forceinline__ void ldsm4(uint32_t r[4], uint32_t addr) {
    asm volatile("ldmatrix.sync.aligned.m8n8.x4.shared.b16 {%0,%1,%2,%3}, [%4];"
                 : "=r"(r[0]), "=r"(r[1]), "=r"(r[2]), "=r"(r[3]) : "r"(addr));
}
__device__ __forceinline__ void ldsm4t(uint32_t r[4], uint32_t addr) {
    asm volatile("ldmatrix.sync.aligned.m8n8.x4.trans.shared.b16 {%0,%1,%2,%3}, [%4];"
                 : "=r"(r[0]), "=r"(r[1]), "=r"(r[2]), "=r"(r[3]) : "r"(addr));
}
__device__ __forceinline__ void mma16816(float c[4],
                                         uint32_t a0, uint32_t a1, uint32_t a2, uint32_t a3,
                                         uint32_t b0, uint32_t b1) {
    asm volatile(
        "mma.sync.aligned.m16n8k16.row.col.f32.bf16.bf16.f32 "
        "{%0,%1,%2,%3}, {%4,%5,%6,%7}, {%8,%9}, {%0,%1,%2,%3};"
        : "+f"(c[0]), "+f"(c[1]), "+f"(c[2]), "+f"(c[3])
        : "r"(a0), "r"(a1), "r"(a2), "r"(a3), "r"(b0), "r"(b1));
}
__device__ __forceinline__ uint32_t pack_bf16_hi(float x, float y) {
    __nv_bfloat16 hx = __float2bfloat16(x), hy = __float2bfloat16(y);
    return (uint32_t)__bfloat16_as_ushort(hx) |
           ((uint32_t)__bfloat16_as_ushort(hy) << 16);
}
__device__ __forceinline__ uint32_t pack_bf16_lo(float x, float y) {
    __nv_bfloat16 hx = __float2bfloat16(x), hy = __float2bfloat16(y);
    __nv_bfloat16 lx = __float2bfloat16(x - __bfloat162float(hx));
    __nv_bfloat16 ly = __float2bfloat16(y - __bfloat162float(hy));
    return (uint32_t)__bfloat16_as_ushort(lx) |
           ((uint32_t)__bfloat16_as_ushort(ly) << 16);
}

// SMEM row stride (128 bf16 + 16B pad)
#define SB_      272
// attention smem offsets
#define OFF_THH  0
#define OFF_THL  34816
#define OFF_PHH  69632
#define OFF_PHL  87040
#define OFF_GH   104448
#define OFF_GL   121856
#define SM_ATTN  139264
// proj/final smem offsets (A hi/lo, B hi/lo; each 128 rows x 272B)
#define OFF_AH   0
#define OFF_AL   34816
#define OFF_BH   69632
#define OFF_BL   104448
#define SM_GEMM  139264

// ===========================================================================
// K1: projections via mma.sync split-bf16 (3 chains), fused maxpool for
//     phi/g.  grid = (196 row tiles, 3 weights), 256 threads.
// ===========================================================================
__global__ __launch_bounds__(256, 1)
void k_projmma(const float* __restrict__ X,
               const float* __restrict__ Wt,
               const float* __restrict__ Wp,
               const float* __restrict__ Wg)
{
    extern __shared__ char smem[];
    const uint32_t sb = smem_u32(smem);
    const int wi = blockIdx.y;
    const float* Wsel = (wi == 0) ? Wt : ((wi == 1) ? Wp : Wg);
    const int r0 = blockIdx.x * 128;      // flattened row base
    const int t  = threadIdx.x;
    const int w  = t >> 5;
    const int lane = t & 31;
    const int tg  = lane >> 3;
    const int tr8 = lane & 7;
    const int aA_row  = ((tg & 1) << 3) + tr8;
    const int aA_colb = (tg & 2) * 8;

    const uint32_t ahA = sb + OFF_AH + (uint32_t)(16 * w + aA_row) * SB_ + aA_colb;
    const uint32_t alA = sb + OFF_AL + (uint32_t)(16 * w + aA_row) * SB_ + aA_colb;
    const uint32_t bhB = sb + OFF_BH + (uint32_t)aA_row * SB_ + aA_colb;
    const uint32_t blB = sb + OFF_BL + (uint32_t)aA_row * SB_ + aA_colb;

    float yv[16][4];
#pragma unroll
    for (int f = 0; f < 16; f++)
#pragma unroll
        for (int j = 0; j < 4; j++) yv[f][j] = 0.f;

    for (int kc = 0; kc < 2; kc++) {
        if (kc) __syncthreads();
        // split-load X tile [128 rows][128 k] and W chunk [128 k][128 n]
#pragma unroll
        for (int q = 0; q < 16; q++) {
            int i = t + 256 * q;
            int r = i >> 5, c4 = (i & 31) * 4;
            float4 v = *(const float4*)&X[(size_t)(r0 + r) * 256 + kc * 128 + c4];
            uint2 h = { pack_bf16_hi(v.x, v.y), pack_bf16_hi(v.z, v.w) };
            uint2 l = { pack_bf16_lo(v.x, v.y), pack_bf16_lo(v.z, v.w) };
            *(uint2*)(smem + OFF_AH + r * SB_ + c4 * 2) = h;
            *(uint2*)(smem + OFF_AL + r * SB_ + c4 * 2) = l;
            float4 wv = *(const float4*)&Wsel[(size_t)(kc * 128 + r) * 128 + c4];
            uint2 wh = { pack_bf16_hi(wv.x, wv.y), pack_bf16_hi(wv.z, wv.w) };
            uint2 wl = { pack_bf16_lo(wv.x, wv.y), pack_bf16_lo(wv.z, wv.w) };
            *(uint2*)(smem + OFF_BH + r * SB_ + c4 * 2) = wh;
            *(uint2*)(smem + OFF_BL + r * SB_ + c4 * 2) = wl;
        }
        __syncthreads();

#pragma unroll
        for (int k = 0; k < 8; k++) {
            uint32_t ah[4], al[4];
            ldsm4(ah, ahA + k * 32);
            ldsm4(al, alA + k * 32);
#pragma unroll
            for (int ng = 0; ng < 8; ng++) {
                uint32_t bh[4];
                ldsm4t(bh, bhB + (uint32_t)(k * 16) * SB_ + ng * 32);
                mma16816(yv[2 * ng],     ah[0], ah[1], ah[2], ah[3], bh[0], bh[1]);
                mma16816(yv[2 * ng + 1], ah[0], ah[1], ah[2], ah[3], bh[2], bh[3]);
                mma16816(yv[2 * ng],     al[0], al[1], al[2], al[3], bh[0], bh[1]);
                mma16816(yv[2 * ng + 1], al[0], al[1], al[2], al[3], bh[2], bh[3]);
            }
#pragma unroll
            for (int ng = 0; ng < 8; ng++) {
                uint32_t bl[4];
                ldsm4t(bl, blB + (uint32_t)(k * 16) * SB_ + ng * 32);
                mma16816(yv[2 * ng],     ah[0], ah[1], ah[2], ah[3], bl[0], bl[1]);
                mma16816(yv[2 * ng + 1], ah[0], ah[1], ah[2], ah[3], bl[2], bl[3]);
            }
        }
    }

    const int q  = lane >> 2;
    const int cb = 2 * (lane & 3);
    if (wi == 0) {
        // theta: split store
        const size_t rA = (size_t)(r0 + 16 * w + q) * 128;
        const size_t rB = rA + 8 * 128;
#pragma unroll
        for (int nf = 0; nf < 16; nf++) {
            int c = nf * 8 + cb;
            *(uint32_t*)&d_th_hi[rA + c] = pack_bf16_hi(yv[nf][0], yv[nf][1]);
            *(uint32_t*)&d_th_lo[rA + c] = pack_bf16_lo(yv[nf][0], yv[nf][1]);
            *(uint32_t*)&d_th_hi[rB + c] = pack_bf16_hi(yv[nf][2], yv[nf][3]);
            *(uint32_t*)&d_th_lo[rB + c] = pack_bf16_lo(yv[nf][2], yv[nf][3]);
        }
    } else {
        // maxpool pairs (rows 2m, 2m+1) via shfl_xor(4), then split store
        __nv_bfloat16* dh = (wi == 1) ? d_ph_hi : d_g_hi;
        __nv_bfloat16* dl = (wi == 1) ? d_ph_lo : d_g_lo;
        float pm[16][4];
#pragma unroll
        for (int nf = 0; nf < 16; nf++)
#pragma unroll
            for (int j = 0; j < 4; j++)
                pm[nf][j] = fmaxf(yv[nf][j],
                                  __shfl_xor_sync(0xffffffffu, yv[nf][j], 4));
        if ((q & 1) == 0) {
            int rpA = (r0 + 16 * w + q) >> 1;          // pooled flattened rows
            int rpB = (r0 + 16 * w + 8 + q) >> 1;
            int bA = rpA / M_, mA = rpA - bA * M_;
            int bB = rpB / M_, mB = rpB - bB * M_;
            size_t dA = ((size_t)bA * MPAD_ + mA) * 128;
            size_t dB = ((size_t)bB * MPAD_ + mB) * 128;
#pragma unroll
            for (int nf = 0; nf < 16; nf++) {
                int c = nf * 8 + cb;
                *(uint32_t*)&dh[dA + c] = pack_bf16_hi(pm[nf][0], pm[nf][1]);
                *(uint32_t*)&dl[dA + c] = pack_bf16_lo(pm[nf][0], pm[nf][1]);
                *(uint32_t*)&dh[dB + c] = pack_bf16_hi(pm[nf][2], pm[nf][3]);
                *(uint32_t*)&dl[dB + c] = pack_bf16_lo(pm[nf][2], pm[nf][3]);
            }
        }
    }
}

// ===========================================================================
// K3: mma.sync flash attention (unchanged math); emits Y pre-split bf16.
// ===========================================================================
__global__ __launch_bounds__(256, 1)
void k_attn3()
{
    extern __shared__ char smem[];
    const uint32_t sb = smem_u32(smem);
    const int b  = blockIdx.y;
    const int n0 = blockIdx.x * 128;
    const int t  = threadIdx.x;
    const int w  = t >> 5;
    const int lane = t & 31;
    const int tg  = lane >> 3;
    const int tr8 = lane & 7;

    const int aA_row  = ((tg & 1) << 3) + tr8;
    const int aA_colb = (tg & 2) * 8;
    const int bp_row  = ((tg & 2) << 2) + tr8;
    const int bp_colb = (tg & 1) * 16;

    const uint32_t thA = sb + OFF_THH + (uint32_t)(16 * w + aA_row) * SB_ + aA_colb;
    const uint32_t tlA = sb + OFF_THL + (uint32_t)(16 * w + aA_row) * SB_ + aA_colb;
    const uint32_t phB = sb + OFF_PHH + (uint32_t)bp_row * SB_ + bp_colb;
    const uint32_t plB = sb + OFF_PHL + (uint32_t)bp_row * SB_ + bp_colb;
    const uint32_t ghB = sb + OFF_GH  + (uint32_t)aA_row * SB_ + aA_colb;
    const uint32_t glB = sb + OFF_GL  + (uint32_t)aA_row * SB_ + aA_colb;

    // ---- load theta tile [128][128] hi+lo ----
#pragma unroll
    for (int q = 0; q < 8; q++) {
        int i = t + 256 * q;
        int r = i >> 4, c8 = (i & 15) * 8;
        int n = n0 + r; if (n > N_ - 1) n = N_ - 1;
        size_t gidx = ((size_t)b * N_ + n) * 128 + c8;
        *(uint4*)(smem + OFF_THH + r * SB_ + c8 * 2) = *(const uint4*)(d_th_hi + gidx);
        *(uint4*)(smem + OFF_THL + r * SB_ + c8 * 2) = *(const uint4*)(d_th_lo + gidx);
    }

    float yv[16][4];
#pragma unroll
    for (int f = 0; f < 16; f++)
#pragma unroll
        for (int j = 0; j < 4; j++) yv[f][j] = 0.f;
    float mA = -1e30f, mB = -1e30f, lA = 0.f, lB = 0.f;

    for (int mt = 0; mt < ITERS; mt++) {
        const int m0 = mt * KV;
        __syncthreads();
#pragma unroll
        for (int q = 0; q < 4; q++) {
            int i = t + 256 * q;
            int r = i >> 4, c8 = (i & 15) * 8;
            size_t gidx = ((size_t)b * MPAD_ + m0 + r) * 128 + c8;
            int so = r * SB_ + c8 * 2;
            *(uint4*)(smem + OFF_PHH + so) = *(const uint4*)(d_ph_hi + gidx);
            *(uint4*)(smem + OFF_PHL + so) = *(const uint4*)(d_ph_lo + gidx);
            *(uint4*)(smem + OFF_GH  + so) = *(const uint4*)(d_g_hi  + gidx);
            *(uint4*)(smem + OFF_GL  + so) = *(const uint4*)(d_g_lo  + gidx);
        }
        __syncthreads();

        float sf[8][4];
#pragma unroll
        for (int f = 0; f < 8; f++)
#pragma unroll
            for (int j = 0; j < 4; j++) sf[f][j] = 0.f;

#pragma unroll
        for (int k = 0; k < 8; k++) {
            uint32_t ah[4], al[4];
            ldsm4(ah, thA + k * 32);
            ldsm4(al, tlA + k * 32);
#pragma unroll
            for (int nb = 0; nb < 4; nb++) {
                uint32_t bh[4];
                ldsm4(bh, phB + (uint32_t)(nb * 16) * SB_ + k * 32);
                mma16816(sf[2 * nb],     ah[0], ah[1], ah[2], ah[3], bh[0], bh[1]);
                mma16816(sf[2 * nb + 1], ah[0], ah[1], ah[2], ah[3], bh[2], bh[3]);
                mma16816(sf[2 * nb],     al[0], al[1], al[2], al[3], bh[0], bh[1]);
                mma16816(sf[2 * nb + 1], al[0], al[1], al[2], al[3], bh[2], bh[3]);
            }
#pragma unroll
            for (int nb = 0; nb < 4; nb++) {
                uint32_t bl[4];
                ldsm4(bl, plB + (uint32_t)(nb * 16) * SB_ + k * 32);
                mma16816(sf[2 * nb],     ah[0], ah[1], ah[2], ah[3], bl[0], bl[1]);
                mma16816(sf[2 * nb + 1], ah[0], ah[1], ah[2], ah[3], bl[2], bl[3]);
            }
        }

        float mxA = -1e30f, mxB = -1e30f;
#pragma unroll
        for (int f = 0; f < 8; f++) {
            mxA = fmaxf(mxA, fmaxf(sf[f][0], sf[f][1]));
            mxB = fmaxf(mxB, fmaxf(sf[f][2], sf[f][3]));
        }
        mxA = fmaxf(mxA, __shfl_xor_sync(0xffffffffu, mxA, 1));
        mxA = fmaxf(mxA, __shfl_xor_sync(0xffffffffu, mxA, 2));
        mxB = fmaxf(mxB, __shfl_xor_sync(0xffffffffu, mxB, 1));
        mxB = fmaxf(mxB, __shfl_xor_sync(0xffffffffu, mxB, 2));
        float mnA = fmaxf(mA, mxA), mnB = fmaxf(mB, mxB);
        float aAc = __expf(mA - mnA), aBc = __expf(mB - mnB);
        mA = mnA; mB = mnB;
        lA *= aAc; lB *= aBc;
#pragma unroll
        for (int f = 0; f < 16; f++) {
            yv[f][0] *= aAc; yv[f][1] *= aAc;
            yv[f][2] *= aBc; yv[f][3] *= aBc;
        }

        uint32_t pah[4][4], pal[4][4];
#pragma unroll
        for (int ks = 0; ks < 4; ks++) {
#pragma unroll
            for (int h = 0; h < 2; h++) {
                int f = 2 * ks + h;
                float p0 = __expf(sf[f][0] - mA);
                float p1 = __expf(sf[f][1] - mA);
                float p2 = __expf(sf[f][2] - mB);
                float p3 = __expf(sf[f][3] - mB);
                lA += p0 + p1; lB += p2 + p3;
                pah[ks][0 + 2 * h] = pack_bf16_hi(p0, p1);
                pah[ks][1 + 2 * h] = pack_bf16_hi(p2, p3);
                pal[ks][0 + 2 * h] = pack_bf16_lo(p0, p1);
                pal[ks][1 + 2 * h] = pack_bf16_lo(p2, p3);
            }
        }

#pragma unroll
        for (int ks = 0; ks < 4; ks++) {
            const uint32_t gb = (uint32_t)(ks * 16) * SB_;
#pragma unroll
            for (int ng = 0; ng < 8; ng++) {
                uint32_t bh[4];
                ldsm4t(bh, ghB + gb + ng * 32);
                mma16816(yv[2 * ng],     pah[ks][0], pah[ks][1], pah[ks][2], pah[ks][3], bh[0], bh[1]);
                mma16816(yv[2 * ng + 1], pah[ks][0], pah[ks][1], pah[ks][2], pah[ks][3], bh[2], bh[3]);
                mma16816(yv[2 * ng],     pal[ks][0], pal[ks][1], pal[ks][2], pal[ks][3], bh[0], bh[1]);
                mma16816(yv[2 * ng + 1], pal[ks][0], pal[ks][1], pal[ks][2], pal[ks][3], bh[2], bh[3]);
            }
#pragma unroll
            for (int ng = 0; ng < 8; ng++) {
                uint32_t bl[4];
                ldsm4t(bl, glB + gb + ng * 32);
                mma16816(yv[2 * ng],     pah[ks][0], pah[ks][1], pah[ks][2], pah[ks][3], bl[0], bl[1]);
                mma16816(yv[2 * ng + 1], pah[ks][0], pah[ks][1], pah[ks][2], pah[ks][3], bl[2], bl[3]);
            }
        }
    }

    lA += __shfl_xor_sync(0xffffffffu, lA, 1);
    lA += __shfl_xor_sync(0xffffffffu, lA, 2);
    lB += __shfl_xor_sync(0xffffffffu, lB, 1);
    lB += __shfl_xor_sync(0xffffffffu, lB, 2);
    const float liA = 1.f / lA, liB = 1.f / lB;

    const int nA = n0 + 16 * w + (lane >> 2);
    const int nB = nA + 8;
    const int cb = 2 * (lane & 3);
    if (nA < N_) {
        size_t base = ((size_t)b * N_ + nA) * 128;
#pragma unroll
        for (int nf = 0; nf < 16; nf++) {
            float v0 = yv[nf][0] * liA, v1 = yv[nf][1] * liA;
            int c = nf * 8 + cb;
            *(uint32_t*)&d_y_hi[base + c] = pack_bf16_hi(v0, v1);
            *(uint32_t*)&d_y_lo[base + c] = pack_bf16_lo(v0, v1);
        }
    }
    if (nB < N_) {
        size_t base = ((size_t)b * N_ + nB) * 128;
#pragma unroll
        for (int nf = 0; nf < 16; nf++) {
            float v0 = yv[nf][2] * liB, v1 = yv[nf][3] * liB;
            int c = nf * 8 + cb;
            *(uint32_t*)&d_y_hi[base + c] = pack_bf16_hi(v0, v1);
            *(uint32_t*)&d_y_lo[base + c] = pack_bf16_lo(v0, v1);
        }
    }
}

// ===========================================================================
// K4: out = x + Y @ Wf via mma.sync split-bf16.  grid = (196, 2 col halves)
// ===========================================================================
__global__ __launch_bounds__(256, 1)
void k_finalmma(const float* __restrict__ X,
                const float* __restrict__ Wf,
                float* __restrict__ out)
{
    extern __shared__ char smem[];
    const uint32_t sb = smem_u32(smem);
    const int r0 = blockIdx.x * 128;
    const int ch = blockIdx.y;           // col half
    const int t  = threadIdx.x;
    const int w  = t >> 5;
    const int lane = t & 31;
    const int tg  = lane >> 3;
    const int tr8 = lane & 7;
    const int aA_row  = ((tg & 1) << 3) + tr8;
    const int aA_colb = (tg & 2) * 8;

    const uint32_t ahA = sb + OFF_AH + (uint32_t)(16 * w + aA_row) * SB_ + aA_colb;
    const uint32_t alA = sb + OFF_AL + (uint32_t)(16 * w + aA_row) * SB_ + aA_colb;
    const uint32_t bhB = sb + OFF_BH + (uint32_t)aA_row * SB_ + aA_colb;
    const uint32_t blB = sb + OFF_BL + (uint32_t)aA_row * SB_ + aA_colb;

    // load Y hi/lo (already bf16)
#pragma unroll
    for (int q = 0; q < 8; q++) {
        int i = t + 256 * q;
        int r = i >> 4, c8 = (i & 15) * 8;
        size_t gidx = (size_t)(r0 + r) * 128 + c8;
        *(uint4*)(smem + OFF_AH + r * SB_ + c8 * 2) = *(const uint4*)(d_y_hi + gidx);
        *(uint4*)(smem + OFF_AL + r * SB_ + c8 * 2) = *(const uint4*)(d_y_lo + gidx);
    }
    // split-load Wf [128 k][128 n of this half]
#pragma unroll
    for (int q = 0; q < 16; q++) {
        int i = t + 256 * q;
        int r = i >> 5, c4 = (i & 31) * 4;
        float4 wv = *(const float4*)&Wf[(size_t)r * 256 + ch * 128 + c4];
        uint2 wh = { pack_bf16_hi(wv.x, wv.y), pack_bf16_hi(wv.z, wv.w) };
        uint2 wl = { pack_bf16_lo(wv.x, wv.y), pack_bf16_lo(wv.z, wv.w) };
        *(uint2*)(smem + OFF_BH + r * SB_ + c4 * 2) = wh;
        *(uint2*)(smem + OFF_BL + r * SB_ + c4 * 2) = wl;
    }
    __syncthreads();

    float yv[16][4];
#pragma unroll
    for (int f = 0; f < 16; f++)
#pragma unroll
        for (int j = 0; j < 4; j++) yv[f][j] = 0.f;

#pragma unroll
    for (int k = 0; k < 8; k++) {
        uint32_t ah[4], al[4];
        ldsm4(ah, ahA + k * 32);
        ldsm4(al, alA + k * 32);
#pragma unroll
        for (int ng = 0; ng < 8; ng++) {
            uint32_t bh[4];
            ldsm4t(bh, bhB + (uint32_t)(k * 16) * SB_ + ng * 32);
            mma16816(yv[2 * ng],     ah[0], ah[1], ah[2], ah[3], bh[0], bh[1]);
            mma16816(yv[2 * ng + 1], ah[0], ah[1], ah[2], ah[3], bh[2], bh[3]);
            mma16816(yv[2 * ng],     al[0], al[1], al[2], al[3], bh[0], bh[1]);
            mma16816(yv[2 * ng + 1], al[0], al[1], al[2], al[3], bh[2], bh[3]);
        }
#pragma unroll
        for (int ng = 0; ng < 8; ng++) {
            uint32_t bl[4];
            ldsm4t(bl, blB + (uint32_t)(k * 16) * SB_ + ng * 32);
            mma16816(yv[2 * ng],     ah[0], ah[1], ah[2], ah[3], bl[0], bl[1]);
            mma16816(yv[2 * ng + 1], ah[0], ah[1], ah[2], ah[3], bl[2], bl[3]);
        }
    }

    // epilogue: residual add + store fp32
    const int q  = lane >> 2;
    const int cb = 2 * (lane & 3);
    const size_t rA = (size_t)(r0 + 16 * w + q) * 256 + ch * 128;
    const size_t rB = rA + 8 * 256;
#pragma unroll
    for (int nf = 0; nf < 16; nf++) {
        int c = nf * 8 + cb;
        float2 xa = *(const float2*)&X[rA + c];
        float2 xb = *(const float2*)&X[rB + c];
        float2 oa = { xa.x + yv[nf][0], xa.y + yv[nf][1] };
        float2 ob = { xb.x + yv[nf][2], xb.y + yv[nf][3] };
        *(float2*)&out[rA + c] = oa;
        *(float2*)&out[rB + c] = ob;
    }
}

// ===========================================================================
extern "C" void kernel_launch(void* const* d_in, const int* in_sizes, int n_in,
                              void* d_out, int out_size)
{
    const float* x  = (const float*)d_in[0];
    const float* wt = (const float*)d_in[1];
    const float* wp = (const float*)d_in[2];
    const float* wg = (const float*)d_in[3];
    const float* wf = (const float*)d_in[4];
    float* out = (float*)d_out;

    cudaFuncSetAttribute(k_projmma, cudaFuncAttributeMaxDynamicSharedMemorySize, SM_GEMM);
    cudaFuncSetAttribute(k_attn3,   cudaFuncAttributeMaxDynamicSharedMemorySize, SM_ATTN);
    cudaFuncSetAttribute(k_finalmma, cudaFuncAttributeMaxDynamicSharedMemorySize, SM_GEMM);

    {
        dim3 grid(ROWS_ / 128, 3);
        k_projmma<<<grid, 256, SM_GEMM>>>(x, wt, wp, wg);
    }
    {
        dim3 grid(25, B_);
        k_attn3<<<grid, 256, SM_ATTN>>>();
    }
    {
        dim3 grid(ROWS_ / 128, 2);
        k_finalmma<<<grid, 256, SM_GEMM>>>(x, wf, out);
    }
}

// round 5
// speedup vs baseline: 3.7285x; 1.2380x over previous
#include <cuda_runtime.h>
#include <cuda_bf16.h>
#include <cstdint>

// Problem constants
#define B_    8
#define C_    256
#define CI_   128
#define N_    3136
#define M_    1568
#define MPAD_ 1600            // 25*64
#define ROWS_ (B_*N_)         // 25088
#define ITERS 25
#define KV    64

// ---------------- scratch (device globals; zero-initialized) --------------
__device__ __nv_bfloat16 d_th_hi[ROWS_*CI_];
__device__ __nv_bfloat16 d_th_lo[ROWS_*CI_];
__device__ __nv_bfloat16 d_ph_hi[B_*MPAD_*CI_];     // [b][m][ci], pad rows stay 0
__device__ __nv_bfloat16 d_ph_lo[B_*MPAD_*CI_];
__device__ __nv_bfloat16 d_g_hi [B_*MPAD_*CI_];
__device__ __nv_bfloat16 d_g_lo [B_*MPAD_*CI_];
__device__ __nv_bfloat16 d_y_hi [ROWS_*CI_];
__device__ __nv_bfloat16 d_y_lo [ROWS_*CI_];
// split-K attention partials
__device__ float d_py[2][ROWS_*CI_];
__device__ float d_pm[2][ROWS_];
__device__ float d_pl[2][ROWS_];

// ======================= helpers ==========================================
__device__ __forceinline__ uint32_t smem_u32(const void* p) {
    uint32_t a;
    asm("{ .reg .u64 t; cvta.to.shared.u64 t, %1; cvt.u32.u64 %0, t; }"
        : "=r"(a) : "l"(p));
    return a;
}
__device__ __forceinline__ void ldsm4(uint32_t r[4], uint32_t addr) {
    asm volatile("ldmatrix.sync.aligned.m8n8.x4.shared.b16 {%0,%1,%2,%3}, [%4];"
                 : "=r"(r[0]), "=r"(r[1]), "=r"(r[2]), "=r"(r[3]) : "r"(addr));
}
__device__ __forceinline__ void ldsm4t(uint32_t r[4], uint32_t addr) {
    asm volatile("ldmatrix.sync.aligned.m8n8.x4.trans.shared.b16 {%0,%1,%2,%3}, [%4];"
                 : "=r"(r[0]), "=r"(r[1]), "=r"(r[2]), "=r"(r[3]) : "r"(addr));
}
__device__ __forceinline__ void mma16816(float c[4],
                                         uint32_t a0, uint32_t a1, uint32_t a2, uint32_t a3,
                                         uint32_t b0, uint32_t b1) {
    asm volatile(
        "mma.sync.aligned.m16n8k16.row.col.f32.bf16.bf16.f32 "
        "{%0,%1,%2,%3}, {%4,%5,%6,%7}, {%8,%9}, {%0,%1,%2,%3};"
        : "+f"(c[0]), "+f"(c[1]), "+f"(c[2]), "+f"(c[3])
        : "r"(a0), "r"(a1), "r"(a2), "r"(a3), "r"(b0), "r"(b1));
}
__device__ __forceinline__ void cp16(uint32_t saddr, const void* gptr) {
    asm volatile("cp.async.cg.shared.global [%0], [%1], 16;"
                 :: "r"(saddr), "l"(gptr));
}
__device__ __forceinline__ uint32_t pack_bf16_hi(float x, float y) {
    __nv_bfloat16 hx = __float2bfloat16(x), hy = __float2bfloat16(y);
    return (uint32_t)__bfloat16_as_ushort(hx) |
           ((uint32_t)__bfloat16_as_ushort(hy) << 16);
}
__device__ __forceinline__ uint32_t pack_bf16_lo(float x, float y) {
    __nv_bfloat16 hx = __float2bfloat16(x), hy = __float2bfloat16(y);
    __nv_bfloat16 lx = __float2bfloat16(x - __bfloat162float(hx));
    __nv_bfloat16 ly = __float2bfloat16(y - __bfloat162float(hy));
    return (uint32_t)__bfloat16_as_ushort(lx) |
           ((uint32_t)__bfloat16_as_ushort(ly) << 16);
}

// SMEM row stride (128 bf16 + 16B pad)
#define SB_      272
// attention smem: theta hi/lo + 2 double-buffered phi/g sets
#define OFF_THH  0
#define OFF_THL  34816
#define BUF0     69632
#define BUFSZ    69632
#define P_PHH    0
#define P_PHL    17408
#define P_GH     34816
#define P_GL     52224
#define SM_ATTN  (BUF0 + 2*BUFSZ)        // 208896
// proj/final smem offsets
#define OFF_AH   0
#define OFF_AL   34816
#define OFF_BH   69632
#define OFF_BL   104448
#define SM_GEMM  139264

// ===========================================================================
// K1: projections via mma.sync split-bf16 (3 chains), fused maxpool.
// ===========================================================================
__global__ __launch_bounds__(256, 1)
void k_projmma(const float* __restrict__ X,
               const float* __restrict__ Wt,
               const float* __restrict__ Wp,
               const float* __restrict__ Wg)
{
    extern __shared__ char smem[];
    const uint32_t sb = smem_u32(smem);
    const int wi = blockIdx.y;
    const float* Wsel = (wi == 0) ? Wt : ((wi == 1) ? Wp : Wg);
    const int r0 = blockIdx.x * 128;
    const int t  = threadIdx.x;
    const int w  = t >> 5;
    const int lane = t & 31;
    const int tg  = lane >> 3;
    const int tr8 = lane & 7;
    const int aA_row  = ((tg & 1) << 3) + tr8;
    const int aA_colb = (tg & 2) * 8;

    const uint32_t ahA = sb + OFF_AH + (uint32_t)(16 * w + aA_row) * SB_ + aA_colb;
    const uint32_t alA = sb + OFF_AL + (uint32_t)(16 * w + aA_row) * SB_ + aA_colb;
    const uint32_t bhB = sb + OFF_BH + (uint32_t)aA_row * SB_ + aA_colb;
    const uint32_t blB = sb + OFF_BL + (uint32_t)aA_row * SB_ + aA_colb;

    float yv[16][4];
#pragma unroll
    for (int f = 0; f < 16; f++)
#pragma unroll
        for (int j = 0; j < 4; j++) yv[f][j] = 0.f;

    for (int kc = 0; kc < 2; kc++) {
        if (kc) __syncthreads();
#pragma unroll
        for (int q = 0; q < 16; q++) {
            int i = t + 256 * q;
            int r = i >> 5, c4 = (i & 31) * 4;
            float4 v = *(const float4*)&X[(size_t)(r0 + r) * 256 + kc * 128 + c4];
            uint2 h = { pack_bf16_hi(v.x, v.y), pack_bf16_hi(v.z, v.w) };
            uint2 l = { pack_bf16_lo(v.x, v.y), pack_bf16_lo(v.z, v.w) };
            *(uint2*)(smem + OFF_AH + r * SB_ + c4 * 2) = h;
            *(uint2*)(smem + OFF_AL + r * SB_ + c4 * 2) = l;
            float4 wv = *(const float4*)&Wsel[(size_t)(kc * 128 + r) * 128 + c4];
            uint2 wh = { pack_bf16_hi(wv.x, wv.y), pack_bf16_hi(wv.z, wv.w) };
            uint2 wl = { pack_bf16_lo(wv.x, wv.y), pack_bf16_lo(wv.z, wv.w) };
            *(uint2*)(smem + OFF_BH + r * SB_ + c4 * 2) = wh;
            *(uint2*)(smem + OFF_BL + r * SB_ + c4 * 2) = wl;
        }
        __syncthreads();

#pragma unroll
        for (int k = 0; k < 8; k++) {
            uint32_t ah[4], al[4];
            ldsm4(ah, ahA + k * 32);
            ldsm4(al, alA + k * 32);
#pragma unroll
            for (int ng = 0; ng < 8; ng++) {
                uint32_t bh[4];
                ldsm4t(bh, bhB + (uint32_t)(k * 16) * SB_ + ng * 32);
                mma16816(yv[2 * ng],     ah[0], ah[1], ah[2], ah[3], bh[0], bh[1]);
                mma16816(yv[2 * ng + 1], ah[0], ah[1], ah[2], ah[3], bh[2], bh[3]);
                mma16816(yv[2 * ng],     al[0], al[1], al[2], al[3], bh[0], bh[1]);
                mma16816(yv[2 * ng + 1], al[0], al[1], al[2], al[3], bh[2], bh[3]);
            }
#pragma unroll
            for (int ng = 0; ng < 8; ng++) {
                uint32_t bl[4];
                ldsm4t(bl, blB + (uint32_t)(k * 16) * SB_ + ng * 32);
                mma16816(yv[2 * ng],     ah[0], ah[1], ah[2], ah[3], bl[0], bl[1]);
                mma16816(yv[2 * ng + 1], ah[0], ah[1], ah[2], ah[3], bl[2], bl[3]);
            }
        }
    }

    const int q  = lane >> 2;
    const int cb = 2 * (lane & 3);
    if (wi == 0) {
        const size_t rA = (size_t)(r0 + 16 * w + q) * 128;
        const size_t rB = rA + 8 * 128;
#pragma unroll
        for (int nf = 0; nf < 16; nf++) {
            int c = nf * 8 + cb;
            *(uint32_t*)&d_th_hi[rA + c] = pack_bf16_hi(yv[nf][0], yv[nf][1]);
            *(uint32_t*)&d_th_lo[rA + c] = pack_bf16_lo(yv[nf][0], yv[nf][1]);
            *(uint32_t*)&d_th_hi[rB + c] = pack_bf16_hi(yv[nf][2], yv[nf][3]);
            *(uint32_t*)&d_th_lo[rB + c] = pack_bf16_lo(yv[nf][2], yv[nf][3]);
        }
    } else {
        __nv_bfloat16* dh = (wi == 1) ? d_ph_hi : d_g_hi;
        __nv_bfloat16* dl = (wi == 1) ? d_ph_lo : d_g_lo;
        float pm[16][4];
#pragma unroll
        for (int nf = 0; nf < 16; nf++)
#pragma unroll
            for (int j = 0; j < 4; j++)
                pm[nf][j] = fmaxf(yv[nf][j],
                                  __shfl_xor_sync(0xffffffffu, yv[nf][j], 4));
        if ((q & 1) == 0) {
            int rpA = (r0 + 16 * w + q) >> 1;
            int rpB = (r0 + 16 * w + 8 + q) >> 1;
            int bA = rpA / M_, mA = rpA - bA * M_;
            int bB = rpB / M_, mB = rpB - bB * M_;
            size_t dA = ((size_t)bA * MPAD_ + mA) * 128;
            size_t dB = ((size_t)bB * MPAD_ + mB) * 128;
#pragma unroll
            for (int nf = 0; nf < 16; nf++) {
                int c = nf * 8 + cb;
                *(uint32_t*)&dh[dA + c] = pack_bf16_hi(pm[nf][0], pm[nf][1]);
                *(uint32_t*)&dl[dA + c] = pack_bf16_lo(pm[nf][0], pm[nf][1]);
                *(uint32_t*)&dh[dB + c] = pack_bf16_hi(pm[nf][2], pm[nf][3]);
                *(uint32_t*)&dl[dB + c] = pack_bf16_lo(pm[nf][2], pm[nf][3]);
            }
        }
    }
}

// ===========================================================================
// K3: split-K flash attention: grid (25, B, 2).  cp.async double-buffered
//     phi/g tiles; partial (m, l, unnormalized Y fp32) per half.
// ===========================================================================
__global__ __launch_bounds__(256, 1)
void k_attn5()
{
    extern __shared__ char smem[];
    const uint32_t sb = smem_u32(smem);
    const int b    = blockIdx.y;
    const int half = blockIdx.z;
    const int n0   = blockIdx.x * 128;
    const int t  = threadIdx.x;
    const int w  = t >> 5;
    const int lane = t & 31;
    const int tg  = lane >> 3;
    const int tr8 = lane & 7;

    const int aA_row  = ((tg & 1) << 3) + tr8;
    const int aA_colb = (tg & 2) * 8;
    const int bp_row  = ((tg & 2) << 2) + tr8;
    const int bp_colb = (tg & 1) * 16;

    const uint32_t thA = sb + OFF_THH + (uint32_t)(16 * w + aA_row) * SB_ + aA_colb;
    const uint32_t tlA = sb + OFF_THL + (uint32_t)(16 * w + aA_row) * SB_ + aA_colb;
    // per-buffer relative offsets
    const uint32_t phB_r = (uint32_t)bp_row * SB_ + bp_colb;
    const uint32_t ghB_r = (uint32_t)aA_row * SB_ + aA_colb;

    const int it0 = (half == 0) ? 0 : 13;
    const int nIt = (half == 0) ? 13 : 12;

    // cp.async load mapping (16 chunks of 16B per thread per tile-set)
    const int ld_r  = t >> 4;             // with q offset below
    const int ld_c8 = (t & 15) * 8;

    // ---- prologue: issue loads for first iter into buf 0 ----
    {
        const int m0 = it0 * KV;
#pragma unroll
        for (int q = 0; q < 4; q++) {
            int r = ld_r + 16 * q;
            size_t gidx = ((size_t)b * MPAD_ + m0 + r) * 128 + ld_c8;
            uint32_t so = sb + BUF0 + (uint32_t)r * SB_ + ld_c8 * 2;
            cp16(so + P_PHH, d_ph_hi + gidx);
            cp16(so + P_PHL, d_ph_lo + gidx);
            cp16(so + P_GH,  d_g_hi  + gidx);
            cp16(so + P_GL,  d_g_lo  + gidx);
        }
        asm volatile("cp.async.commit_group;");
    }

    // ---- load theta tile [128][128] hi+lo (overlaps with cp.async) ----
#pragma unroll
    for (int q = 0; q < 8; q++) {
        int i = t + 256 * q;
        int r = i >> 4, c8 = (i & 15) * 8;
        int n = n0 + r; if (n > N_ - 1) n = N_ - 1;
        size_t gidx = ((size_t)b * N_ + n) * 128 + c8;
        *(uint4*)(smem + OFF_THH + r * SB_ + c8 * 2) = *(const uint4*)(d_th_hi + gidx);
        *(uint4*)(smem + OFF_THL + r * SB_ + c8 * 2) = *(const uint4*)(d_th_lo + gidx);
    }

    float yv[16][4];
#pragma unroll
    for (int f = 0; f < 16; f++)
#pragma unroll
        for (int j = 0; j < 4; j++) yv[f][j] = 0.f;
    float mA = -1e30f, mB = -1e30f, lA = 0.f, lB = 0.f;

    for (int ii = 0; ii < nIt; ii++) {
        const uint32_t bufc = sb + BUF0 + (uint32_t)(ii & 1) * BUFSZ;
        if (ii + 1 < nIt) {
            // issue next iter's loads into the other buffer
            const int m0n = (it0 + ii + 1) * KV;
            const uint32_t bufn = sb + BUF0 + (uint32_t)((ii + 1) & 1) * BUFSZ;
#pragma unroll
            for (int q = 0; q < 4; q++) {
                int r = ld_r + 16 * q;
                size_t gidx = ((size_t)b * MPAD_ + m0n + r) * 128 + ld_c8;
                uint32_t so = bufn + (uint32_t)r * SB_ + ld_c8 * 2;
                cp16(so + P_PHH, d_ph_hi + gidx);
                cp16(so + P_PHL, d_ph_lo + gidx);
                cp16(so + P_GH,  d_g_hi  + gidx);
                cp16(so + P_GL,  d_g_lo  + gidx);
            }
            asm volatile("cp.async.commit_group;");
            asm volatile("cp.async.wait_group 1;");
        } else {
            asm volatile("cp.async.wait_group 0;");
        }
        __syncthreads();

        const uint32_t phB = bufc + P_PHH + phB_r;
        const uint32_t plB = bufc + P_PHL + phB_r;
        const uint32_t ghB = bufc + P_GH  + ghB_r;
        const uint32_t glB = bufc + P_GL  + ghB_r;

        float sf[8][4];
#pragma unroll
        for (int f = 0; f < 8; f++)
#pragma unroll
            for (int j = 0; j < 4; j++) sf[f][j] = 0.f;

#pragma unroll
        for (int k = 0; k < 8; k++) {
            uint32_t ah[4], al[4];
            ldsm4(ah, thA + k * 32);
            ldsm4(al, tlA + k * 32);
#pragma unroll
            for (int nb = 0; nb < 4; nb++) {
                uint32_t bh[4];
                ldsm4(bh, phB + (uint32_t)(nb * 16) * SB_ + k * 32);
                mma16816(sf[2 * nb],     ah[0], ah[1], ah[2], ah[3], bh[0], bh[1]);
                mma16816(sf[2 * nb + 1], ah[0], ah[1], ah[2], ah[3], bh[2], bh[3]);
                mma16816(sf[2 * nb],     al[0], al[1], al[2], al[3], bh[0], bh[1]);
                mma16816(sf[2 * nb + 1], al[0], al[1], al[2], al[3], bh[2], bh[3]);
            }
#pragma unroll
            for (int nb = 0; nb < 4; nb++) {
                uint32_t bl[4];
                ldsm4(bl, plB + (uint32_t)(nb * 16) * SB_ + k * 32);
                mma16816(sf[2 * nb],     ah[0], ah[1], ah[2], ah[3], bl[0], bl[1]);
                mma16816(sf[2 * nb + 1], ah[0], ah[1], ah[2], ah[3], bl[2], bl[3]);
            }
        }

        float mxA = -1e30f, mxB = -1e30f;
#pragma unroll
        for (int f = 0; f < 8; f++) {
            mxA = fmaxf(mxA, fmaxf(sf[f][0], sf[f][1]));
            mxB = fmaxf(mxB, fmaxf(sf[f][2], sf[f][3]));
        }
        mxA = fmaxf(mxA, __shfl_xor_sync(0xffffffffu, mxA, 1));
        mxA = fmaxf(mxA, __shfl_xor_sync(0xffffffffu, mxA, 2));
        mxB = fmaxf(mxB, __shfl_xor_sync(0xffffffffu, mxB, 1));
        mxB = fmaxf(mxB, __shfl_xor_sync(0xffffffffu, mxB, 2));
        float mnA = fmaxf(mA, mxA), mnB = fmaxf(mB, mxB);
        float aAc = __expf(mA - mnA), aBc = __expf(mB - mnB);
        mA = mnA; mB = mnB;
        lA *= aAc; lB *= aBc;
#pragma unroll
        for (int f = 0; f < 16; f++) {
            yv[f][0] *= aAc; yv[f][1] *= aAc;
            yv[f][2] *= aBc; yv[f][3] *= aBc;
        }

        uint32_t pah[4][4], pal[4][4];
#pragma unroll
        for (int ks = 0; ks < 4; ks++) {
#pragma unroll
            for (int h = 0; h < 2; h++) {
                int f = 2 * ks + h;
                float p0 = __expf(sf[f][0] - mA);
                float p1 = __expf(sf[f][1] - mA);
                float p2 = __expf(sf[f][2] - mB);
                float p3 = __expf(sf[f][3] - mB);
                lA += p0 + p1; lB += p2 + p3;
                pah[ks][0 + 2 * h] = pack_bf16_hi(p0, p1);
                pah[ks][1 + 2 * h] = pack_bf16_hi(p2, p3);
                pal[ks][0 + 2 * h] = pack_bf16_lo(p0, p1);
                pal[ks][1 + 2 * h] = pack_bf16_lo(p2, p3);
            }
        }

#pragma unroll
        for (int ks = 0; ks < 4; ks++) {
            const uint32_t gb = (uint32_t)(ks * 16) * SB_;
#pragma unroll
            for (int ng = 0; ng < 8; ng++) {
                uint32_t bh[4];
                ldsm4t(bh, ghB + gb + ng * 32);
                mma16816(yv[2 * ng],     pah[ks][0], pah[ks][1], pah[ks][2], pah[ks][3], bh[0], bh[1]);
                mma16816(yv[2 * ng + 1], pah[ks][0], pah[ks][1], pah[ks][2], pah[ks][3], bh[2], bh[3]);
                mma16816(yv[2 * ng],     pal[ks][0], pal[ks][1], pal[ks][2], pal[ks][3], bh[0], bh[1]);
                mma16816(yv[2 * ng + 1], pal[ks][0], pal[ks][1], pal[ks][2], pal[ks][3], bh[2], bh[3]);
            }
#pragma unroll
            for (int ng = 0; ng < 8; ng++) {
                uint32_t bl[4];
                ldsm4t(bl, glB + gb + ng * 32);
                mma16816(yv[2 * ng],     pah[ks][0], pah[ks][1], pah[ks][2], pah[ks][3], bl[0], bl[1]);
                mma16816(yv[2 * ng + 1], pah[ks][0], pah[ks][1], pah[ks][2], pah[ks][3], bl[2], bl[3]);
            }
        }
        __syncthreads();
    }

    // ---- partial reduce within quad, store partials ----
    lA += __shfl_xor_sync(0xffffffffu, lA, 1);
    lA += __shfl_xor_sync(0xffffffffu, lA, 2);
    lB += __shfl_xor_sync(0xffffffffu, lB, 1);
    lB += __shfl_xor_sync(0xffffffffu, lB, 2);

    const int nA = n0 + 16 * w + (lane >> 2);
    const int nB = nA + 8;
    const int cb = 2 * (lane & 3);
    if (nA < N_) {
        size_t base = ((size_t)b * N_ + nA) * 128;
#pragma unroll
        for (int nf = 0; nf < 16; nf++) {
            float2 v = { yv[nf][0], yv[nf][1] };
            *(float2*)&d_py[half][base + nf * 8 + cb] = v;
        }
        if ((lane & 3) == 0) {
            d_pm[half][b * N_ + nA] = mA;
            d_pl[half][b * N_ + nA] = lA;
        }
    }
    if (nB < N_) {
        size_t base = ((size_t)b * N_ + nB) * 128;
#pragma unroll
        for (int nf = 0; nf < 16; nf++) {
            float2 v = { yv[nf][2], yv[nf][3] };
            *(float2*)&d_py[half][base + nf * 8 + cb] = v;
        }
        if ((lane & 3) == 0) {
            d_pm[half][b * N_ + nB] = mB;
            d_pl[half][b * N_ + nB] = lB;
        }
    }
}

// ===========================================================================
// K3b: combine split-K halves -> split-bf16 Y
// ===========================================================================
__global__ __launch_bounds__(256)
void k_combine()
{
    int idx = blockIdx.x * 256 + threadIdx.x;    // one float4 per thread
    if (idx >= ROWS_ * 32) return;
    int row = idx >> 5;
    int c4  = (idx & 31) * 4;
    float m0 = d_pm[0][row], m1 = d_pm[1][row];
    float l0 = d_pl[0][row], l1 = d_pl[1][row];
    float m  = fmaxf(m0, m1);
    float w0 = __expf(m0 - m), w1 = __expf(m1 - m);
    float inv = 1.f / (l0 * w0 + l1 * w1);
    w0 *= inv; w1 *= inv;
    size_t base = (size_t)row * 128 + c4;
    float4 y0 = *(const float4*)&d_py[0][base];
    float4 y1 = *(const float4*)&d_py[1][base];
    float v0 = y0.x * w0 + y1.x * w1;
    float v1 = y0.y * w0 + y1.y * w1;
    float v2 = y0.z * w0 + y1.z * w1;
    float v3 = y0.w * w0 + y1.w * w1;
    uint2 h = { pack_bf16_hi(v0, v1), pack_bf16_hi(v2, v3) };
    uint2 l = { pack_bf16_lo(v0, v1), pack_bf16_lo(v2, v3) };
    *(uint2*)&d_y_hi[base] = h;
    *(uint2*)&d_y_lo[base] = l;
}

// ===========================================================================
// K4: out = x + Y @ Wf via mma.sync split-bf16
// ===========================================================================
__global__ __launch_bounds__(256, 1)
void k_finalmma(const float* __restrict__ X,
                const float* __restrict__ Wf,
                float* __restrict__ out)
{
    extern __shared__ char smem[];
    const uint32_t sb = smem_u32(smem);
    const int r0 = blockIdx.x * 128;
    const int ch = blockIdx.y;
    const int t  = threadIdx.x;
    const int w  = t >> 5;
    const int lane = t & 31;
    const int tg  = lane >> 3;
    const int tr8 = lane & 7;
    const int aA_row  = ((tg & 1) << 3) + tr8;
    const int aA_colb = (tg & 2) * 8;

    const uint32_t ahA = sb + OFF_AH + (uint32_t)(16 * w + aA_row) * SB_ + aA_colb;
    const uint32_t alA = sb + OFF_AL + (uint32_t)(16 * w + aA_row) * SB_ + aA_colb;
    const uint32_t bhB = sb + OFF_BH + (uint32_t)aA_row * SB_ + aA_colb;
    const uint32_t blB = sb + OFF_BL + (uint32_t)aA_row * SB_ + aA_colb;

#pragma unroll
    for (int q = 0; q < 8; q++) {
        int i = t + 256 * q;
        int r = i >> 4, c8 = (i & 15) * 8;
        size_t gidx = (size_t)(r0 + r) * 128 + c8;
        *(uint4*)(smem + OFF_AH + r * SB_ + c8 * 2) = *(const uint4*)(d_y_hi + gidx);
        *(uint4*)(smem + OFF_AL + r * SB_ + c8 * 2) = *(const uint4*)(d_y_lo + gidx);
    }
#pragma unroll
    for (int q = 0; q < 16; q++) {
        int i = t + 256 * q;
        int r = i >> 5, c4 = (i & 31) * 4;
        float4 wv = *(const float4*)&Wf[(size_t)r * 256 + ch * 128 + c4];
        uint2 wh = { pack_bf16_hi(wv.x, wv.y), pack_bf16_hi(wv.z, wv.w) };
        uint2 wl = { pack_bf16_lo(wv.x, wv.y), pack_bf16_lo(wv.z, wv.w) };
        *(uint2*)(smem + OFF_BH + r * SB_ + c4 * 2) = wh;
        *(uint2*)(smem + OFF_BL + r * SB_ + c4 * 2) = wl;
    }
    __syncthreads();

    float yv[16][4];
#pragma unroll
    for (int f = 0; f < 16; f++)
#pragma unroll
        for (int j = 0; j < 4; j++) yv[f][j] = 0.f;

#pragma unroll
    for (int k = 0; k < 8; k++) {
        uint32_t ah[4], al[4];
        ldsm4(ah, ahA + k * 32);
        ldsm4(al, alA + k * 32);
#pragma unroll
        for (int ng = 0; ng < 8; ng++) {
            uint32_t bh[4];
            ldsm4t(bh, bhB + (uint32_t)(k * 16) * SB_ + ng * 32);
            mma16816(yv[2 * ng],     ah[0], ah[1], ah[2], ah[3], bh[0], bh[1]);
            mma16816(yv[2 * ng + 1], ah[0], ah[1], ah[2], ah[3], bh[2], bh[3]);
            mma16816(yv[2 * ng],     al[0], al[1], al[2], al[3], bh[0], bh[1]);
            mma16816(yv[2 * ng + 1], al[0], al[1], al[2], al[3], bh[2], bh[3]);
        }
#pragma unroll
        for (int ng = 0; ng < 8; ng++) {
            uint32_t bl[4];
            ldsm4t(bl, blB + (uint32_t)(k * 16) * SB_ + ng * 32);
            mma16816(yv[2 * ng],     ah[0], ah[1], ah[2], ah[3], bl[0], bl[1]);
            mma16816(yv[2 * ng + 1], ah[0], ah[1], ah[2], ah[3], bl[2], bl[3]);
        }
    }

    const int q  = lane >> 2;
    const int cb = 2 * (lane & 3);
    const size_t rA = (size_t)(r0 + 16 * w + q) * 256 + ch * 128;
    const size_t rB = rA + 8 * 256;
#pragma unroll
    for (int nf = 0; nf < 16; nf++) {
        int c = nf * 8 + cb;
        float2 xa = *(const float2*)&X[rA + c];
        float2 xb = *(const float2*)&X[rB + c];
        float2 oa = { xa.x + yv[nf][0], xa.y + yv[nf][1] };
        float2 ob = { xb.x + yv[nf][2], xb.y + yv[nf][3] };
        *(float2*)&out[rA + c] = oa;
        *(float2*)&out[rB + c] = ob;
    }
}

// ===========================================================================
extern "C" void kernel_launch(void* const* d_in, const int* in_sizes, int n_in,
                              void* d_out, int out_size)
{
    const float* x  = (const float*)d_in[0];
    const float* wt = (const float*)d_in[1];
    const float* wp = (const float*)d_in[2];
    const float* wg = (const float*)d_in[3];
    const float* wf = (const float*)d_in[4];
    float* out = (float*)d_out;

    cudaFuncSetAttribute(k_projmma,  cudaFuncAttributeMaxDynamicSharedMemorySize, SM_GEMM);
    cudaFuncSetAttribute(k_attn5,    cudaFuncAttributeMaxDynamicSharedMemorySize, SM_ATTN);
    cudaFuncSetAttribute(k_finalmma, cudaFuncAttributeMaxDynamicSharedMemorySize, SM_GEMM);

    {
        dim3 grid(ROWS_ / 128, 3);
        k_projmma<<<grid, 256, SM_GEMM>>>(x, wt, wp, wg);
    }
    {
        dim3 grid(25, B_, 2);
        k_attn5<<<grid, 256, SM_ATTN>>>();
    }
    {
        k_combine<<<(ROWS_ * 32 + 255) / 256, 256>>>();
    }
    {
        dim3 grid(ROWS_ / 128, 2);
        k_finalmma<<<grid, 256, SM_GEMM>>>(x, wf, out);
    }
}